// round 3
// baseline (speedup 1.0000x reference)
#include <cuda_runtime.h>
#include <math.h>

// Problem constants
#define Bc 32
#define Sc 1024
#define Ec 256
#define Hc 256
#define NCTA 128      // 64 CTAs per direction, 4 hidden units each
#define TPB 256       // 8 warps

// Output section offsets (floats)
#define OUT_C 16777216UL          // S*B*2H
#define OUT_S 33554432UL          // 2 * S*B*2H

// SMEM layout (float offsets)
#define OFF_WA   0        // [16 cols][772]   z-projection weights (x|h|s stacked on k)
#define OFF_WB   12352    // [8 cols][516]    r-projection weights (x|h stacked on k)
#define OFF_BA   16480    // [16]
#define OFF_BB   16496    // [16]
#define OFF_SIN  16512    // [32 b][772]      staged x(0:256) h(256:512) s(512:768)
#define OFF_PRED 41216    // [8 warps][520]   k-split partials
#define OFF_CLOC 45376    // [4 jj][32 b]     cell state (CTA-local, persistent)
#define OFF_SLOC 45504    // [8 c][32 b]      shared state (CTA-local, persistent)
#define OFF_HTMP 45760    // [4 jj][32 b]
#define OFF_MASK 45888    // [32]
#define SMEM_FLOATS 45920
#define SMEM_BYTES (SMEM_FLOATS * 4)

// Global scratch (cross-CTA communication).
__device__ float g_h[2 * Bc * Hc];     // [dir][b][j]
__device__ float g_s[4 * Bc * Hc];     // [dir][share][b][j]
__device__ unsigned g_arrive[NCTA * 32];  // one 128B line per CTA
__device__ unsigned g_release32[32];

__global__ void init_kernel() {
    int tid = blockIdx.x * blockDim.x + threadIdx.x;
    int stride = gridDim.x * blockDim.x;
    for (int i = tid; i < 2 * Bc * Hc; i += stride) g_h[i] = 0.0f;
    for (int i = tid; i < 4 * Bc * Hc; i += stride) g_s[i] = 0.0f;
    for (int i = tid; i < NCTA * 32; i += stride) g_arrive[i] = 0u;
    if (tid < 32) g_release32[tid] = 0u;
}

__device__ __forceinline__ float sigf(float x) { return 1.0f / (1.0f + expf(-x)); }

// Packed dual-fp32 FMA (sm_103a): d = a*b + d elementwise on 2 floats.
__device__ __forceinline__ void fma2(unsigned long long& d,
                                     const unsigned long long a,
                                     const unsigned long long b) {
    asm("fma.rn.f32x2 %0, %1, %2, %0;" : "+l"(d) : "l"(a), "l"(b));
}
__device__ __forceinline__ float pair_sum(unsigned long long v) {
    float lo = __uint_as_float((unsigned int)(v & 0xffffffffULL));
    float hi = __uint_as_float((unsigned int)(v >> 32));
    return lo + hi;
}

__device__ __forceinline__ void st_rel(unsigned* p, unsigned v) {
    asm volatile("st.release.gpu.u32 [%0], %1;" :: "l"(p), "r"(v) : "memory");
}
__device__ __forceinline__ unsigned ld_acq(const unsigned* p) {
    unsigned v;
    asm volatile("ld.acquire.gpu.u32 %0, [%1];" : "=r"(v) : "l"(p) : "memory");
    return v;
}

// cp.async helpers
__device__ __forceinline__ void cp16(const float* smem_ptr, const float* gptr) {
    unsigned sa = (unsigned)__cvta_generic_to_shared(smem_ptr);
    asm volatile("cp.async.cg.shared.global [%0], [%1], 16;" :: "r"(sa), "l"(gptr));
}
__device__ __forceinline__ void cp4(const float* smem_ptr, const float* gptr) {
    unsigned sa = (unsigned)__cvta_generic_to_shared(smem_ptr);
    asm volatile("cp.async.ca.shared.global [%0], [%1], 4;" :: "r"(sa), "l"(gptr));
}
#define CP_COMMIT asm volatile("cp.async.commit_group;")
#define CP_WAIT0  asm volatile("cp.async.wait_group 0;")

// Flag-based grid barrier: per-CTA arrival lines + single release word.
__device__ __forceinline__ void grid_barrier(int cta, unsigned e) {
    __syncthreads();              // all block work (incl. global stores) done
    if (cta == 0) {
        if (threadIdx.x < 32) {
            const int lane = threadIdx.x;
            #pragma unroll
            for (int j = 0; j < 4; ++j) {
                const int idx = j * 32 + lane;
                if (idx != 0) {
                    const unsigned* f = &g_arrive[idx * 32];
                    while (ld_acq(f) < e) { }
                }
            }
            __syncwarp();
            if (lane == 0) st_rel(&g_release32[0], e);
        }
        __syncthreads();
    } else {
        if (threadIdx.x == 0) {
            st_rel(&g_arrive[cta * 32], e);
            while (ld_acq(&g_release32[0]) < e) { }
        }
        __syncthreads();
    }
}

__global__ void __launch_bounds__(TPB, 1) bislstm_kernel(
    const float* __restrict__ inputs, const float* __restrict__ mask,
    const float* __restrict__ Wx,   const float* __restrict__ Wh,
    const float* __restrict__ Ws,   const float* __restrict__ bz,
    const float* __restrict__ Wrx,  const float* __restrict__ Wrh,
    const float* __restrict__ br,
    const float* __restrict__ Wx_r, const float* __restrict__ Wh_r,
    const float* __restrict__ Ws_r, const float* __restrict__ bz_r,
    const float* __restrict__ Wrx_r,const float* __restrict__ Wrh_r,
    const float* __restrict__ br_r,
    const int* __restrict__ idx_ptr, float* __restrict__ out)
{
    extern __shared__ float sm[];
    const int tid  = threadIdx.x;
    const int warp = tid >> 5;
    const int lane = tid & 31;
    const int cta  = blockIdx.x;
    const int dir  = cta >> 6;           // 0 = fwd, 1 = rev
    const int cid  = cta & 63;
    const int jbase = cid * 4;           // this CTA's 4 hidden units
    const int idxv = *idx_ptr;

    const float* pWx  = dir ? Wx_r  : Wx;
    const float* pWh  = dir ? Wh_r  : Wh;
    const float* pWs  = dir ? Ws_r  : Ws;
    const float* pB   = dir ? bz_r  : bz;
    const float* pWrx = dir ? Wrx_r : Wrx;
    const float* pWrh = dir ? Wrh_r : Wrh;
    const float* pBr  = dir ? br_r  : br;

    // ---- Load weight slices into SMEM (once) ----
    for (int i = tid; i < 16 * 768; i += TPB) {
        int k = i >> 4, c = i & 15;
        int gate = c >> 2, jj = c & 3;
        int gcol = gate * Hc + jbase + jj;
        float v;
        if (k < 256)      v = pWx[(size_t)k * (4 * Hc) + gcol];
        else if (k < 512) v = pWh[(size_t)(k - 256) * (4 * Hc) + gcol];
        else              v = pWs[(size_t)(k - 512) * (4 * Hc) + gcol];
        sm[OFF_WA + c * 772 + k] = v;
    }
    for (int i = tid; i < 8 * 512; i += TPB) {
        int k = i >> 3, c = i & 7;
        int kk = c >> 2, jj = c & 3;
        int j = jbase + jj;
        float v;
        if (k < 256) v = pWrx[(size_t)kk * Ec * Hc + (size_t)k * Hc + j];
        else         v = pWrh[(size_t)kk * Hc * Hc + (size_t)(k - 256) * Hc + j];
        sm[OFF_WB + c * 516 + k] = v;
    }
    if (tid < 16) {
        int gate = tid >> 2, jj = tid & 3;
        sm[OFF_BA + tid] = pB[gate * Hc + jbase + jj];
    }
    if (tid < 8) {
        int kk = tid >> 2, jj = tid & 3;
        sm[OFF_BB + tid] = pBr[kk * Hc + jbase + jj];
    }
    if (tid < 128) sm[OFF_CLOC + tid] = 0.0f;
    sm[OFF_SLOC + tid] = 0.0f;
    // zero h segment of SIN (phase A of n=0 reads zeros)
    for (int i = tid; i < 32 * 256; i += TPB) {
        int b = i >> 8, r = i & 255;
        sm[OFF_SIN + b * 772 + 256 + r] = 0.0f;
    }
    // prefetch x_0 and mask_0
    {
        const int t0 = dir ? (Sc - 1) : 0;
        for (int i = tid; i < 2048; i += TPB) {
            int b = i >> 6, k4 = i & 63;
            cp16(&sm[OFF_SIN + b * 772 + k4 * 4],
                 inputs + ((size_t)b * Sc + t0) * Ec + k4 * 4);
        }
        if (tid < 32) cp4(&sm[OFF_MASK + tid], mask + (size_t)tid * Sc + t0);
        CP_COMMIT;
    }

    unsigned e = 0;

    for (int n = 0; n < Sc; ++n) {
        const int t = dir ? (Sc - 1 - n) : n;

        // ===== Phase A staging: s_prev[idx] (x, h, mask already in SMEM) =====
        {
            const float* ssrc = g_s + (size_t)(dir * 2 + idxv) * (Bc * Hc);
            for (int i = tid; i < 2048; i += TPB) {
                int b = i >> 6, k4 = i & 63;
                cp16(&sm[OFF_SIN + b * 772 + 512 + k4 * 4], ssrc + b * 256 + k4 * 4);
            }
            CP_COMMIT; CP_WAIT0;
        }
        __syncthreads();

        // ===== Phase A compute: z partials (warp k-split, 96 k/warp, f32x2) =====
        {
            unsigned long long acc2[16];
            #pragma unroll
            for (int c = 0; c < 16; ++c) acc2[c] = 0ULL;
            const int k0 = warp * 96;
            const float* inb = &sm[OFF_SIN + lane * 772 + k0];
            const float* wb  = &sm[OFF_WA + k0];
            #pragma unroll 2
            for (int kb = 0; kb < 24; ++kb) {
                ulonglong2 xv = *reinterpret_cast<const ulonglong2*>(inb + kb * 4);
                #pragma unroll
                for (int c = 0; c < 16; ++c) {
                    ulonglong2 wv = *reinterpret_cast<const ulonglong2*>(wb + c * 772 + kb * 4);
                    fma2(acc2[c], xv.x, wv.x);
                    fma2(acc2[c], xv.y, wv.y);
                }
            }
            #pragma unroll
            for (int c = 0; c < 16; ++c)
                sm[OFF_PRED + warp * 520 + c * 32 + lane] = pair_sum(acc2[c]);
        }
        __syncthreads();

        // ===== fused reduce + gates + mask blend (128 threads) =====
        if (tid < 128) {
            const int jj = tid >> 5, b = tid & 31;
            float zi = sm[OFF_BA + jj];
            float zf = sm[OFF_BA + 4 + jj];
            float zg = sm[OFF_BA + 8 + jj];
            float zo = sm[OFF_BA + 12 + jj];
            #pragma unroll
            for (int w = 0; w < 8; ++w) {
                const float* p = &sm[OFF_PRED + w * 520 + b];
                zi += p[(jj     ) * 32];
                zf += p[(jj +  4) * 32];
                zg += p[(jj +  8) * 32];
                zo += p[(jj + 12) * 32];
            }
            const float cold = sm[OFF_CLOC + tid];
            const float hold = sm[OFF_SIN + b * 772 + 256 + jbase + jj];
            const float m    = sm[OFF_MASK + b];
            const float cn = sigf(zf) * cold + sigf(zi) * tanhf(zg);
            const float hn = sigf(zo) * tanhf(cn);
            const float h = m * hn + (1.0f - m) * hold;
            const float c = m * cn + (1.0f - m) * cold;
            sm[OFF_CLOC + tid] = c;
            sm[OFF_HTMP + tid] = h;
        }
        __syncthreads();

        // publish h, write h/c outputs
        if (tid < 32) {
            const int b = tid;
            float4 hv = make_float4(sm[OFF_HTMP + b],      sm[OFF_HTMP + 32 + b],
                                    sm[OFF_HTMP + 64 + b], sm[OFF_HTMP + 96 + b]);
            float4 cv = make_float4(sm[OFF_CLOC + b],      sm[OFF_CLOC + 32 + b],
                                    sm[OFF_CLOC + 64 + b], sm[OFF_CLOC + 96 + b]);
            float* hp = g_h + (size_t)dir * (Bc * Hc) + b * 256 + jbase;
            *reinterpret_cast<float4*>(hp) = hv;
            size_t ob = (size_t)t * (Bc * 512) + (size_t)b * 512 + dir * 256 + jbase;
            *reinterpret_cast<float4*>(out + ob) = hv;
            *reinterpret_cast<float4*>(out + OUT_C + ob) = cv;
        }
        grid_barrier(cta, ++e);

        // ===== Phase B staging: h_new (full) =====
        {
            const float* hsrc = g_h + (size_t)dir * (Bc * Hc);
            for (int i = tid; i < 2048; i += TPB) {
                int b = i >> 6, k4 = i & 63;
                cp16(&sm[OFF_SIN + b * 772 + 256 + k4 * 4], hsrc + b * 256 + k4 * 4);
            }
            CP_COMMIT; CP_WAIT0;
        }
        __syncthreads();

        // ===== Phase B compute: r partials (warp k-split, 64 k/warp) =====
        {
            unsigned long long acc2[8];
            #pragma unroll
            for (int c = 0; c < 8; ++c) acc2[c] = 0ULL;
            const int k0 = warp * 64;
            const float* inb = &sm[OFF_SIN + lane * 772 + k0];
            const float* wb  = &sm[OFF_WB + k0];
            #pragma unroll 2
            for (int kb = 0; kb < 16; ++kb) {
                ulonglong2 xv = *reinterpret_cast<const ulonglong2*>(inb + kb * 4);
                #pragma unroll
                for (int c = 0; c < 8; ++c) {
                    ulonglong2 wv = *reinterpret_cast<const ulonglong2*>(wb + c * 516 + kb * 4);
                    fma2(acc2[c], xv.x, wv.x);
                    fma2(acc2[c], xv.y, wv.y);
                }
            }
            #pragma unroll
            for (int c = 0; c < 8; ++c)
                sm[OFF_PRED + warp * 520 + c * 32 + lane] = pair_sum(acc2[c]);
        }
        __syncthreads();

        // ===== fused reduce + s update (256 threads) =====
        {
            const int o = tid;
            const int c = o >> 5, b = o & 31;
            const int jj = c & 3;
            float z = sm[OFF_BB + c];
            #pragma unroll
            for (int w = 0; w < 8; ++w) z += sm[OFF_PRED + w * 520 + o];
            const float r    = sigf(z);
            const float sold = sm[OFF_SLOC + o];
            const float cc   = sm[OFF_CLOC + jj * 32 + b];
            const float m    = sm[OFF_MASK + b];
            const float sn   = r * sold + (1.0f - r) * cc;
            sm[OFF_SLOC + o] = m * sn + (1.0f - m) * sold;
        }
        __syncthreads();

        // publish s + write s outputs; prefetch next x/mask
        if (tid < 64) {
            const int kk = tid >> 5, b = tid & 31;
            const int base = (kk * 4) * 32 + b;
            float4 sv = make_float4(sm[OFF_SLOC + base],      sm[OFF_SLOC + base + 32],
                                    sm[OFF_SLOC + base + 64], sm[OFF_SLOC + base + 96]);
            *reinterpret_cast<float4*>(
                g_s + (size_t)(dir * 2 + kk) * (Bc * Hc) + b * 256 + jbase) = sv;
            size_t ob = (size_t)kk * ((size_t)Sc * Bc * 512)
                      + (size_t)t * (Bc * 512) + (size_t)b * 512 + dir * 256 + jbase;
            *reinterpret_cast<float4*>(out + OUT_S + ob) = sv;
        }
        if (n + 1 < Sc) {
            const int tn = dir ? (Sc - 2 - n) : (n + 1);
            for (int i = tid; i < 2048; i += TPB) {
                int b = i >> 6, k4 = i & 63;
                cp16(&sm[OFF_SIN + b * 772 + k4 * 4],
                     inputs + ((size_t)b * Sc + tn) * Ec + k4 * 4);
            }
            if (tid < 32) cp4(&sm[OFF_MASK + tid], mask + (size_t)tid * Sc + tn);
            CP_COMMIT;
        }
        grid_barrier(cta, ++e);
    }
}

extern "C" void kernel_launch(void* const* d_in, const int* in_sizes, int n_in,
                              void* d_out, int out_size) {
    (void)in_sizes; (void)n_in; (void)out_size;
    cudaFuncSetAttribute(bislstm_kernel,
                         cudaFuncAttributeMaxDynamicSharedMemorySize, SMEM_BYTES);
    init_kernel<<<64, 256>>>();
    bislstm_kernel<<<NCTA, TPB, SMEM_BYTES>>>(
        (const float*)d_in[0],  (const float*)d_in[1],
        (const float*)d_in[2],  (const float*)d_in[3],
        (const float*)d_in[4],  (const float*)d_in[5],
        (const float*)d_in[6],  (const float*)d_in[7],
        (const float*)d_in[8],
        (const float*)d_in[9],  (const float*)d_in[10],
        (const float*)d_in[11], (const float*)d_in[12],
        (const float*)d_in[13], (const float*)d_in[14],
        (const float*)d_in[15],
        (const int*)d_in[16],   (float*)d_out);
}

// round 4
// speedup vs baseline: 1.6045x; 1.6045x over previous
#include <cuda_runtime.h>
#include <math.h>

// Problem constants
#define Bc 32
#define Sc 1024
#define Ec 256
#define Hc 256
#define NCTA 128      // 64 CTAs per direction, 4 hidden units each
#define TPB 256       // 8 warps

// Output section offsets (floats)
#define OUT_C 16777216UL          // S*B*2H
#define OUT_S 33554432UL          // 2 * S*B*2H

// SMEM layout (float offsets)
#define OFF_WA   0        // [16 cols][772]   z-projection weights (x|h|s stacked on k)
#define OFF_WB   12352    // [8 cols][516]    r-projection weights (x|h stacked on k)
#define OFF_BA   16480    // [16]
#define OFF_BB   16496    // [16]
#define OFF_SIN  16512    // [32 b][772]      staged x(0:256) h(256:512) s(512:768)
#define OFF_PRED 41216    // [8 warps][520]   k-split partials
#define OFF_CLOC 45376    // [4 jj][32 b]     cell state (CTA-local, persistent)
#define OFF_SLOC 45504    // [8 c][32 b]      shared state (CTA-local, persistent)
#define OFF_HTMP 45760    // [4 jj][32 b]
#define OFF_MASK 45888    // [32]
#define SMEM_FLOATS 45920
#define SMEM_BYTES (SMEM_FLOATS * 4)

// Global scratch (cross-CTA communication).
__device__ float g_h[2 * Bc * Hc];     // [dir][b][j]
__device__ float g_s[4 * Bc * Hc];     // [dir][share][b][j]
__device__ uint4 g_flags4[32];         // 128 packed epoch flags (512B)

__global__ void init_kernel() {
    int tid = blockIdx.x * blockDim.x + threadIdx.x;
    int stride = gridDim.x * blockDim.x;
    for (int i = tid; i < 2 * Bc * Hc; i += stride) g_h[i] = 0.0f;
    for (int i = tid; i < 4 * Bc * Hc; i += stride) g_s[i] = 0.0f;
    if (tid < 128) reinterpret_cast<unsigned*>(g_flags4)[tid] = 0u;
}

__device__ __forceinline__ float sigf(float x) { return 1.0f / (1.0f + expf(-x)); }

// Packed dual-fp32 FMA (sm_103a): d = a*b + d elementwise on 2 floats.
__device__ __forceinline__ void fma2(unsigned long long& d,
                                     const unsigned long long a,
                                     const unsigned long long b) {
    asm("fma.rn.f32x2 %0, %1, %2, %0;" : "+l"(d) : "l"(a), "l"(b));
}
__device__ __forceinline__ float pair_sum(unsigned long long v) {
    float lo = __uint_as_float((unsigned int)(v & 0xffffffffULL));
    float hi = __uint_as_float((unsigned int)(v >> 32));
    return lo + hi;
}

// cp.async helpers
__device__ __forceinline__ void cp16(const float* smem_ptr, const float* gptr) {
    unsigned sa = (unsigned)__cvta_generic_to_shared(smem_ptr);
    asm volatile("cp.async.cg.shared.global [%0], [%1], 16;" :: "r"(sa), "l"(gptr));
}
__device__ __forceinline__ void cp4(const float* smem_ptr, const float* gptr) {
    unsigned sa = (unsigned)__cvta_generic_to_shared(smem_ptr);
    asm volatile("cp.async.ca.shared.global [%0], [%1], 4;" :: "r"(sa), "l"(gptr));
}
#define CP_COMMIT asm volatile("cp.async.commit_group;")
#define CP_WAIT0  asm volatile("cp.async.wait_group 0;")

// Decentralized barrier: arrive = release-store own flag; wait = warp0 polls all
// 128 flags with ONE vector load per lane (128 flags = 32 lanes x uint4).
__device__ __forceinline__ void barrier_arrive(int cta, unsigned e) {
    __syncthreads();   // all block work (global stores) issued before release
    if (threadIdx.x == 0) {
        unsigned* f = reinterpret_cast<unsigned*>(g_flags4) + cta;
        asm volatile("st.release.gpu.u32 [%0], %1;" :: "l"(f), "r"(e) : "memory");
    }
}
__device__ __forceinline__ void barrier_wait(unsigned e) {
    if (threadIdx.x < 32) {
        const uint4* fp = &g_flags4[threadIdx.x];
        bool ok;
        do {
            uint4 v;
            asm volatile("ld.relaxed.gpu.v4.u32 {%0,%1,%2,%3}, [%4];"
                         : "=r"(v.x), "=r"(v.y), "=r"(v.z), "=r"(v.w)
                         : "l"(fp) : "memory");
            ok = (v.x >= e) && (v.y >= e) && (v.z >= e) && (v.w >= e);
        } while (!__all_sync(0xffffffffu, ok));
        asm volatile("fence.acq_rel.gpu;" ::: "memory");
    }
    __syncthreads();
}

// Accumulate 32-k segment: NC columns, weight row stride WSTR (floats).
template<int NC, int WSTR>
__device__ __forceinline__ void accum_part(const float* __restrict__ sm,
                                           unsigned long long* acc,
                                           int in_base, int w_base) {
    const float* inb = sm + in_base;
    const float* wb  = sm + w_base;
    #pragma unroll
    for (int kb = 0; kb < 8; ++kb) {
        ulonglong2 xv = *reinterpret_cast<const ulonglong2*>(inb + kb * 4);
        #pragma unroll
        for (int c = 0; c < NC; ++c) {
            ulonglong2 wv = *reinterpret_cast<const ulonglong2*>(wb + c * WSTR + kb * 4);
            fma2(acc[c], xv.x, wv.x);
            fma2(acc[c], xv.y, wv.y);
        }
    }
}

__global__ void __launch_bounds__(TPB, 1) bislstm_kernel(
    const float* __restrict__ inputs, const float* __restrict__ mask,
    const float* __restrict__ Wx,   const float* __restrict__ Wh,
    const float* __restrict__ Ws,   const float* __restrict__ bz,
    const float* __restrict__ Wrx,  const float* __restrict__ Wrh,
    const float* __restrict__ br,
    const float* __restrict__ Wx_r, const float* __restrict__ Wh_r,
    const float* __restrict__ Ws_r, const float* __restrict__ bz_r,
    const float* __restrict__ Wrx_r,const float* __restrict__ Wrh_r,
    const float* __restrict__ br_r,
    const int* __restrict__ idx_ptr, float* __restrict__ out)
{
    extern __shared__ float sm[];
    const int tid  = threadIdx.x;
    const int warp = tid >> 5;
    const int lane = tid & 31;
    const int cta  = blockIdx.x;
    const int dir  = cta >> 6;           // 0 = fwd, 1 = rev
    const int cid  = cta & 63;
    const int jbase = cid * 4;           // this CTA's 4 hidden units
    const int idxv = *idx_ptr;
    const int w32 = warp * 32;           // this warp's k-offset inside each 256-segment

    const float* pWx  = dir ? Wx_r  : Wx;
    const float* pWh  = dir ? Wh_r  : Wh;
    const float* pWs  = dir ? Ws_r  : Ws;
    const float* pB   = dir ? bz_r  : bz;
    const float* pWrx = dir ? Wrx_r : Wrx;
    const float* pWrh = dir ? Wrh_r : Wrh;
    const float* pBr  = dir ? br_r  : br;

    // ---- Load weight slices into SMEM (once) ----
    for (int i = tid; i < 16 * 768; i += TPB) {
        int k = i >> 4, c = i & 15;
        int gate = c >> 2, jj = c & 3;
        int gcol = gate * Hc + jbase + jj;
        float v;
        if (k < 256)      v = pWx[(size_t)k * (4 * Hc) + gcol];
        else if (k < 512) v = pWh[(size_t)(k - 256) * (4 * Hc) + gcol];
        else              v = pWs[(size_t)(k - 512) * (4 * Hc) + gcol];
        sm[OFF_WA + c * 772 + k] = v;
    }
    for (int i = tid; i < 8 * 512; i += TPB) {
        int k = i >> 3, c = i & 7;
        int kk = c >> 2, jj = c & 3;
        int j = jbase + jj;
        float v;
        if (k < 256) v = pWrx[(size_t)kk * Ec * Hc + (size_t)k * Hc + j];
        else         v = pWrh[(size_t)kk * Hc * Hc + (size_t)(k - 256) * Hc + j];
        sm[OFF_WB + c * 516 + k] = v;
    }
    if (tid < 16) {
        int gate = tid >> 2, jj = tid & 3;
        sm[OFF_BA + tid] = pB[gate * Hc + jbase + jj];
    }
    if (tid < 8) {
        int kk = tid >> 2, jj = tid & 3;
        sm[OFF_BB + tid] = pBr[kk * Hc + jbase + jj];
    }
    if (tid < 128) sm[OFF_CLOC + tid] = 0.0f;
    sm[OFF_SLOC + tid] = 0.0f;
    // zero h segment of SIN (step 0 reads h = 0)
    for (int i = tid; i < 32 * 256; i += TPB) {
        int b = i >> 8, r = i & 255;
        sm[OFF_SIN + b * 772 + 256 + r] = 0.0f;
    }
    // prefetch x_0 and mask_0
    {
        const int t0 = dir ? (Sc - 1) : 0;
        for (int i = tid; i < 2048; i += TPB) {
            int b = i >> 6, k4 = i & 63;
            cp16(&sm[OFF_SIN + b * 772 + k4 * 4],
                 inputs + ((size_t)b * Sc + t0) * Ec + k4 * 4);
        }
        if (tid < 32) cp4(&sm[OFF_MASK + tid], mask + (size_t)tid * Sc + t0);
        CP_COMMIT;
    }

    unsigned e = 0;
    // z accumulators: h-part of step n is carried here across barrier 2 (zeros for n=0)
    unsigned long long acc2[16];
    #pragma unroll
    for (int c = 0; c < 16; ++c) acc2[c] = 0ULL;

    for (int n = 0; n < Sc; ++n) {
        const int t = dir ? (Sc - 1 - n) : n;

        // ===== stage s_prev[idx] (L2) ; x/mask already arriving via cp.async =====
        CP_WAIT0;
        {
            const float* ssrc = g_s + (size_t)(dir * 2 + idxv) * (Bc * Hc);
            #pragma unroll
            for (int i = tid; i < 2048; i += TPB) {
                int b = i >> 6, k4 = i & 63;
                float4 v = __ldcg(reinterpret_cast<const float4*>(ssrc + b * 256 + k4 * 4));
                *reinterpret_cast<float4*>(&sm[OFF_SIN + b * 772 + 512 + k4 * 4]) = v;
            }
        }
        __syncthreads();

        // ===== z: x-part + s-part (h-part already in acc2) =====
        accum_part<16, 772>(sm, acc2, OFF_SIN + lane * 772 + w32,       OFF_WA + w32);
        accum_part<16, 772>(sm, acc2, OFF_SIN + lane * 772 + 512 + w32, OFF_WA + 512 + w32);
        #pragma unroll
        for (int c = 0; c < 16; ++c)
            sm[OFF_PRED + warp * 520 + c * 32 + lane] = pair_sum(acc2[c]);
        __syncthreads();

        // ===== fused reduce + gates + mask blend (128 threads) =====
        if (tid < 128) {
            const int jj = tid >> 5, b = tid & 31;
            float zi = sm[OFF_BA + jj];
            float zf = sm[OFF_BA + 4 + jj];
            float zg = sm[OFF_BA + 8 + jj];
            float zo = sm[OFF_BA + 12 + jj];
            #pragma unroll
            for (int w = 0; w < 8; ++w) {
                const float* p = &sm[OFF_PRED + w * 520 + b];
                zi += p[(jj     ) * 32];
                zf += p[(jj +  4) * 32];
                zg += p[(jj +  8) * 32];
                zo += p[(jj + 12) * 32];
            }
            const float cold = sm[OFF_CLOC + tid];
            const float hold = sm[OFF_SIN + b * 772 + 256 + jbase + jj];
            const float m    = sm[OFF_MASK + b];
            const float cn = sigf(zf) * cold + sigf(zi) * tanhf(zg);
            const float hn = sigf(zo) * tanhf(cn);
            const float h = m * hn + (1.0f - m) * hold;
            const float c = m * cn + (1.0f - m) * cold;
            sm[OFF_CLOC + tid] = c;
            sm[OFF_HTMP + tid] = h;
        }
        __syncthreads();

        // ===== publish h + h/c outputs =====
        if (tid < 32) {
            const int b = tid;
            float4 hv = make_float4(sm[OFF_HTMP + b],      sm[OFF_HTMP + 32 + b],
                                    sm[OFF_HTMP + 64 + b], sm[OFF_HTMP + 96 + b]);
            float4 cv = make_float4(sm[OFF_CLOC + b],      sm[OFF_CLOC + 32 + b],
                                    sm[OFF_CLOC + 64 + b], sm[OFF_CLOC + 96 + b]);
            float* hp = g_h + (size_t)dir * (Bc * Hc) + b * 256 + jbase;
            *reinterpret_cast<float4*>(hp) = hv;
            size_t ob = (size_t)t * (Bc * 512) + (size_t)b * 512 + dir * 256 + jbase;
            *reinterpret_cast<float4*>(out + ob) = hv;
            *reinterpret_cast<float4*>(out + OUT_C + ob) = cv;
        }
        barrier_arrive(cta, ++e);

        // ----- overlap barrier-1 settle with r's x-part -----
        unsigned long long accB[8];
        #pragma unroll
        for (int c = 0; c < 8; ++c) accB[c] = 0ULL;
        accum_part<8, 516>(sm, accB, OFF_SIN + lane * 772 + w32, OFF_WB + w32);
        barrier_wait(e);

        // ===== stage h_new (L2) =====
        {
            const float* hsrc = g_h + (size_t)dir * (Bc * Hc);
            #pragma unroll
            for (int i = tid; i < 2048; i += TPB) {
                int b = i >> 6, k4 = i & 63;
                float4 v = __ldcg(reinterpret_cast<const float4*>(hsrc + b * 256 + k4 * 4));
                *reinterpret_cast<float4*>(&sm[OFF_SIN + b * 772 + 256 + k4 * 4]) = v;
            }
        }
        __syncthreads();

        // ===== r: h-part =====
        accum_part<8, 516>(sm, accB, OFF_SIN + lane * 772 + 256 + w32, OFF_WB + 256 + w32);
        #pragma unroll
        for (int c = 0; c < 8; ++c)
            sm[OFF_PRED + warp * 520 + c * 32 + lane] = pair_sum(accB[c]);
        __syncthreads();

        // ===== fused reduce + s update (256 threads) =====
        {
            const int o = tid;
            const int c = o >> 5, b = o & 31;
            const int jj = c & 3;
            float z = sm[OFF_BB + c];
            #pragma unroll
            for (int w = 0; w < 8; ++w) z += sm[OFF_PRED + w * 520 + o];
            const float r    = sigf(z);
            const float sold = sm[OFF_SLOC + o];
            const float cc   = sm[OFF_CLOC + jj * 32 + b];
            const float m    = sm[OFF_MASK + b];
            const float sn   = r * sold + (1.0f - r) * cc;
            sm[OFF_SLOC + o] = m * sn + (1.0f - m) * sold;
        }
        __syncthreads();

        // ===== publish s + s outputs; prefetch x_{n+1}/mask =====
        if (tid < 64) {
            const int kk = tid >> 5, b = tid & 31;
            const int base = (kk * 4) * 32 + b;
            float4 sv = make_float4(sm[OFF_SLOC + base],      sm[OFF_SLOC + base + 32],
                                    sm[OFF_SLOC + base + 64], sm[OFF_SLOC + base + 96]);
            *reinterpret_cast<float4*>(
                g_s + (size_t)(dir * 2 + kk) * (Bc * Hc) + b * 256 + jbase) = sv;
            size_t ob = (size_t)kk * ((size_t)Sc * Bc * 512)
                      + (size_t)t * (Bc * 512) + (size_t)b * 512 + dir * 256 + jbase;
            *reinterpret_cast<float4*>(out + OUT_S + ob) = sv;
        }
        if (n + 1 < Sc) {
            const int tn = dir ? (Sc - 2 - n) : (n + 1);
            for (int i = tid; i < 2048; i += TPB) {
                int b = i >> 6, k4 = i & 63;
                cp16(&sm[OFF_SIN + b * 772 + k4 * 4],
                     inputs + ((size_t)b * Sc + tn) * Ec + k4 * 4);
            }
            if (tid < 32) cp4(&sm[OFF_MASK + tid], mask + (size_t)tid * Sc + tn);
            CP_COMMIT;
        }
        barrier_arrive(cta, ++e);

        // ----- overlap barrier-2 settle with z's h-part for step n+1 -----
        #pragma unroll
        for (int c = 0; c < 16; ++c) acc2[c] = 0ULL;
        accum_part<16, 772>(sm, acc2, OFF_SIN + lane * 772 + 256 + w32, OFF_WA + 256 + w32);
        barrier_wait(e);
    }
}

extern "C" void kernel_launch(void* const* d_in, const int* in_sizes, int n_in,
                              void* d_out, int out_size) {
    (void)in_sizes; (void)n_in; (void)out_size;
    cudaFuncSetAttribute(bislstm_kernel,
                         cudaFuncAttributeMaxDynamicSharedMemorySize, SMEM_BYTES);
    init_kernel<<<64, 256>>>();
    bislstm_kernel<<<NCTA, TPB, SMEM_BYTES>>>(
        (const float*)d_in[0],  (const float*)d_in[1],
        (const float*)d_in[2],  (const float*)d_in[3],
        (const float*)d_in[4],  (const float*)d_in[5],
        (const float*)d_in[6],  (const float*)d_in[7],
        (const float*)d_in[8],
        (const float*)d_in[9],  (const float*)d_in[10],
        (const float*)d_in[11], (const float*)d_in[12],
        (const float*)d_in[13], (const float*)d_in[14],
        (const float*)d_in[15],
        (const int*)d_in[16],   (float*)d_out);
}